// round 11
// baseline (speedup 1.0000x reference)
#include <cuda_runtime.h>
#include <cstdint>
#include <cstring>

#define Bv 4
#define Nv 512
#define Dv 256
#define Lv 64

typedef unsigned long long ull;

// w-folded projection, two layouts
__device__ float g_xh [Bv * Lv * Nv];   // [b][l][n]
__device__ float g_xht[Bv * Nv * Lv];   // [b][n][l]
// per-(tile,row,jq) partial sums (plain overwrite each replay)
__device__ float g_rows[128 * 16 * 4];
// device barrier (replay-safe: count resets, release monotone)
__device__ unsigned g_count = 0, g_release = 0;
// per-tile monotone arrival counters
__device__ unsigned g_tflag[128];

static __device__ __forceinline__ ull pk2(float a) {
    ull r;
    asm("mov.b64 %0, {%1, %2};" : "=l"(r) : "f"(a), "f"(a));
    return r;
}
// packed f32x2 add, result reinterpreted as two floats (register pair halves)
static __device__ __forceinline__ float2 add2f(ull a, ull b) {
    ull r;
    asm("add.rn.f32x2 %0, %1, %2;" : "=l"(r) : "l"(a), "l"(b));
    float2 f;
    memcpy(&f, &r, 8);
    return f;
}

// ---------------------------------------------------------------------------
// Grid 512 = tile(128) x jq(4).  256 threads, 4 CTAs/SM (53 KB smem).
// Smem floats: si2[0,2048) | psum[2048,4096) | adjs[4096,6144)
// Phase-A overlay (jq==0 only): xs[0,4352) | Wt[4352,13568)
// ---------------------------------------------------------------------------
__global__ __launch_bounds__(256, 4) void fused_kernel(
    const float* __restrict__ x, const float* __restrict__ adj,
    const float* __restrict__ W, const float* __restrict__ lw,
    float* __restrict__ out) {
    extern __shared__ float sm[];
    ull*   si2  = (ull*)sm;          // [64][16] {-wv,-wv}
    float* psum = sm + 2048;         // [16][128]
    float* adjs = sm + 4096;         // [16][128]
    float* xs   = sm;                // [256][17] (phase A)
    float* Wt   = sm + 4352;         // [256][36] (phase A)

    int bid  = blockIdx.x;
    int tile = bid >> 2, jq = bid & 3;
    int b    = tile >> 5, i0 = (tile & 31) << 4;
    int tid  = threadIdx.x;

    if (jq != 0) {
        // early adj tile stage (overlaps peers' phase A)
        for (int idx = tid; idx < 512; idx += 256) {
            int r = idx >> 5, c = idx & 31;
            ((float4*)adjs)[idx] =
                *(const float4*)&adj[(size_t)(b * Nv + i0 + r) * Nv + jq * 128 + c * 4];
        }
    } else {
        // ---------- Phase A: weighted projection of this tile's 16 rows ----
        for (int idx = tid; idx < 4096; idx += 256) {
            int rr = idx >> 8, d = idx & 255;
            xs[d * 17 + rr] = x[(b * Nv + i0 + rr) * Dv + d];
        }
        int r  = tid & 15;
        int lg = tid >> 4;             // 16 l-groups of 2
        float av[4];
#pragma unroll
        for (int pass = 0; pass < 2; ++pass) {
            for (int idx = tid; idx < 8192; idx += 256) {
                int lp = idx >> 8, d = idx & 255;
                Wt[d * 36 + lp] = W[(pass * 32 + lp) * Dv + d];
            }
            __syncthreads();
            float c0 = 0.f, c1 = 0.f;
#pragma unroll 8
            for (int d = 0; d < 256; ++d) {
                float  xv = xs[d * 17 + r];
                float2 wv = *(const float2*)&Wt[d * 36 + lg * 2];
                c0 = fmaf(xv, wv.x, c0);
                c1 = fmaf(xv, wv.y, c1);
            }
            int l0 = pass * 32 + lg * 2;
            c0 *= lw[l0];
            c1 *= lw[l0 + 1];
            g_xh[b * (Lv * Nv) + (l0    ) * Nv + i0 + r] = c0;
            g_xh[b * (Lv * Nv) + (l0 + 1) * Nv + i0 + r] = c1;
            *(float2*)&g_xht[(size_t)(b * Nv + i0 + r) * Lv + l0] =
                make_float2(c0, c1);
            av[pass * 2 + 0] = c0;
            av[pass * 2 + 1] = c1;
            __syncthreads();
        }
        // si2 (overwrites xs region; synced above)
        si2[(lg * 2 + 0) * 16 + r]      = pk2(-av[0]);
        si2[(lg * 2 + 1) * 16 + r]      = pk2(-av[1]);
        si2[(32 + lg * 2 + 0) * 16 + r] = pk2(-av[2]);
        si2[(32 + lg * 2 + 1) * 16 + r] = pk2(-av[3]);
        __syncthreads();
        // late adj stage (adjs overlaps Wt region, now dead)
        for (int idx = tid; idx < 512; idx += 256) {
            int r2 = idx >> 5, c = idx & 31;
            ((float4*)adjs)[idx] =
                *(const float4*)&adj[(size_t)(b * Nv + i0 + r2) * Nv + c * 4];
        }
    }

    // ---------------- Device-wide barrier #1 -------------------------------
    if (tid == 0) {
        __threadfence();
        unsigned snap = *(volatile unsigned*)&g_release;
        unsigned old  = atomicAdd(&g_count, 1);
        if (old == gridDim.x - 1) {
            g_count = 0;
            __threadfence();
            atomicAdd(&g_release, 1);
        } else {
            while (*(volatile unsigned*)&g_release == snap) __nanosleep(32);
        }
        __threadfence();
    }
    __syncthreads();

    // si2 staging for jq!=0 CTAs (coalesced from g_xht)
    if (jq != 0) {
        int r  = tid >> 4;
        int l0 = (tid & 15) * 4;
        float4 v = *(const float4*)&g_xht[(size_t)(b * Nv + i0 + r) * Lv + l0];
        si2[(l0 + 0) * 16 + r] = pk2(-v.x);
        si2[(l0 + 1) * 16 + r] = pk2(-v.y);
        si2[(l0 + 2) * 16 + r] = pk2(-v.z);
        si2[(l0 + 3) * 16 + r] = pk2(-v.w);
        __syncthreads();
    }

    // ---------------- Mainloop: j streamed from L1/L2 ----------------------
    int w    = tid >> 5;
    int lane = tid & 31;
    int rg   = w & 3;           // rows rg*4..rg*4+3
    int lh   = w >> 2;          // l half
    const float* jp  = g_xh + b * (Lv * Nv) + (size_t)(lh * 32) * Nv + jq * 128 + lane * 4;
    const ull*   sip = si2 + (lh * 32) * 16 + rg * 4;

    float acc[4][4] = {};
#pragma unroll
    for (int l = 0; l < 32; ++l) {
        ulonglong2 j01 = *(const ulonglong2*)(jp + (size_t)l * Nv);
        ulonglong2 nab = *(const ulonglong2*)(sip + l * 16);
        ulonglong2 ncd = *(const ulonglong2*)(sip + l * 16 + 2);
        float2 f;
        f = add2f(j01.x, nab.x); acc[0][0] += fabsf(f.x); acc[0][1] += fabsf(f.y);
        f = add2f(j01.y, nab.x); acc[0][2] += fabsf(f.x); acc[0][3] += fabsf(f.y);
        f = add2f(j01.x, nab.y); acc[1][0] += fabsf(f.x); acc[1][1] += fabsf(f.y);
        f = add2f(j01.y, nab.y); acc[1][2] += fabsf(f.x); acc[1][3] += fabsf(f.y);
        f = add2f(j01.x, ncd.x); acc[2][0] += fabsf(f.x); acc[2][1] += fabsf(f.y);
        f = add2f(j01.y, ncd.x); acc[2][2] += fabsf(f.x); acc[2][3] += fabsf(f.y);
        f = add2f(j01.x, ncd.y); acc[3][0] += fabsf(f.x); acc[3][1] += fabsf(f.y);
        f = add2f(j01.y, ncd.y); acc[3][2] += fabsf(f.x); acc[3][3] += fabsf(f.y);
    }

    // ---------------- merge l-halves through psum --------------------------
    if (lh == 0) {
#pragma unroll
        for (int r = 0; r < 4; ++r)
            *(float4*)&psum[(rg * 4 + r) * 128 + lane * 4] =
                make_float4(acc[r][0], acc[r][1], acc[r][2], acc[r][3]);
    }
    __syncthreads();

    float e[4][4];
    if (lh == 1) {
        float srow[4];
#pragma unroll
        for (int r = 0; r < 4; ++r) {
            int row = rg * 4 + r;
            float4 p  = *(const float4*)&psum[row * 128 + lane * 4];
            float4 a4 = *(const float4*)&adjs[row * 128 + lane * 4];
            float v, s;
            v = p.x + acc[r][0]; v = v > 0.f ? v : 0.01f * v; e[r][0] = a4.x * __expf(v);
            v = p.y + acc[r][1]; v = v > 0.f ? v : 0.01f * v; e[r][1] = a4.y * __expf(v);
            v = p.z + acc[r][2]; v = v > 0.f ? v : 0.01f * v; e[r][2] = a4.z * __expf(v);
            v = p.w + acc[r][3]; v = v > 0.f ? v : 0.01f * v; e[r][3] = a4.w * __expf(v);
            s = e[r][0] + e[r][1] + e[r][2] + e[r][3];
#pragma unroll
            for (int o = 16; o; o >>= 1)
                s += __shfl_xor_sync(0xffffffffu, s, o);
            srow[r] = s;
        }
        if (lane == 0) {
#pragma unroll
            for (int r = 0; r < 4; ++r)
                g_rows[(tile * 16 + rg * 4 + r) * 4 + jq] = srow[r];
            __threadfence();
        }
    }
    __syncthreads();

    // ---------------- per-tile barrier (4 jq CTAs) --------------------------
    if (tid == 0) {
        unsigned old    = atomicAdd(&g_tflag[tile], 1);
        unsigned target = (old & ~3u) + 4;
        while (*(volatile unsigned*)&g_tflag[tile] < target) __nanosleep(32);
        __threadfence();
    }
    __syncthreads();

    // ---------------- normalize + store -------------------------------------
    if (lh == 1) {
#pragma unroll
        for (int r = 0; r < 4; ++r) {
            int row = rg * 4 + r;
            float4 s4 = __ldcg((const float4*)&g_rows[(tile * 16 + row) * 4]);
            float rs = 1.0f / (s4.x + s4.y + s4.z + s4.w);
            float4 o4;
            o4.x = e[r][0] * rs + 1e-10f;
            o4.y = e[r][1] * rs + 1e-10f;
            o4.z = e[r][2] * rs + 1e-10f;
            o4.w = e[r][3] * rs + 1e-10f;
            *(float4*)&out[(size_t)(b * Nv + i0 + row) * Nv + jq * 128 + lane * 4] = o4;
        }
    }
}

extern "C" void kernel_launch(void* const* d_in, const int* in_sizes, int n_in,
                              void* d_out, int out_size) {
    (void)in_sizes; (void)n_in; (void)out_size;
    const float* x   = (const float*)d_in[0];
    const float* adj = (const float*)d_in[1];
    const float* W   = (const float*)d_in[2];
    const float* lw  = (const float*)d_in[3];
    float* out = (float*)d_out;

    const int smem = 13568 * 4;   // 54272 B -> 4 CTAs/SM (217 KB of 228)
    cudaFuncSetAttribute(fused_kernel,
                         cudaFuncAttributeMaxDynamicSharedMemorySize, smem);
    cudaFuncSetAttribute(fused_kernel,
                         cudaFuncAttributePreferredSharedMemoryCarveout,
                         cudaSharedmemCarveoutMaxShared);

    fused_kernel<<<512, 256, smem>>>(x, adj, W, lw, out);
}

// round 12
// speedup vs baseline: 1.7743x; 1.7743x over previous
#include <cuda_runtime.h>
#include <cstdint>

#define Bv 4
#define Nv 512
#define Dv 256
#define Lv 64

typedef unsigned long long ull;

// w-folded projection [b][l][n] (512 KB) and symmetric dist buffer (4 MB)
__device__ float g_xh[Bv * Lv * Nv];
__device__ float g_dist[Bv * Nv * Nv];
// device barrier (replay-safe: count resets, release monotone)
__device__ unsigned g_count = 0, g_release = 0;

__device__ __forceinline__ ull pk2(float a) {
    ull r;
    asm("mov.b64 %0, {%1, %2};" : "=l"(r) : "f"(a), "f"(a));
    return r;
}
__device__ __forceinline__ ull add2(ull a, ull b) {
    ull r;
    asm("add.rn.f32x2 %0, %1, %2;" : "=l"(r) : "l"(a), "l"(b));
    return r;
}
__device__ __forceinline__ float lo2(ull a) {
    float x, y;
    asm("mov.b64 {%0, %1}, %2;" : "=f"(x), "=f"(y) : "l"(a));
    return x;
}
__device__ __forceinline__ float hi2(ull a) {
    float x, y;
    asm("mov.b64 {%0, %1}, %2;" : "=f"(x), "=f"(y) : "l"(a));
    return y;
}

// Standard grid-sync pattern (all CTAs co-resident: grid 128 <= 148 SMs)
__device__ __forceinline__ void grid_barrier(int tid) {
    __syncthreads();
    if (tid == 0) {
        __threadfence();
        unsigned snap = *(volatile unsigned*)&g_release;
        unsigned old  = atomicAdd(&g_count, 1);
        if (old == 127u) {
            g_count = 0;
            __threadfence();
            atomicAdd(&g_release, 1);
        } else {
            while (*(volatile unsigned*)&g_release == snap) __nanosleep(32);
        }
        __threadfence();
    }
    __syncthreads();
}

// ---------------------------------------------------------------------------
// Grid 128 = (b, tile t of 16 rows), 1024 threads, ~94 KB smem.
// Symmetric band: tile t computes j-blocks t+1..t+16 (256 cols), writes the
// block + its transpose into g_dist; diagonal block computed from si2.
// Smem floats: sjb[0,17408)=64x272 | si2[17408,19456) | psum[19456,23552)
//              | red[23552,23616); phase-A overlay Wt@0 (256x68), xs@17408.
// ---------------------------------------------------------------------------
__global__ __launch_bounds__(1024, 1) void fused_kernel(
    const float* __restrict__ x, const float* __restrict__ adj,
    const float* __restrict__ W, const float* __restrict__ lw,
    float* __restrict__ out) {
    extern __shared__ float sm[];
    float* sjb  = sm;                       // [64][272] j-band
    ull*   si2  = (ull*)(sm + 17408);       // [64][16] {-wv,-wv}
    float* psum = sm + 19456;               // [16][256]
    float* red  = sm + 23552;               // [32]
    float* Wt = sm;                         // [256][68] (phase A)
    float* xs = sm + 17408;                 // [256][17] (phase A)

    int bid = blockIdx.x;
    int b = bid >> 5, t = bid & 31;
    int i0 = t << 4;
    int tid = threadIdx.x;

    // ---------------- Phase A: weighted projection of own 16 rows ----------
    for (int idx = tid; idx < 4096; idx += 1024) {
        int rr = idx >> 8, d = idx & 255;
        xs[d * 17 + rr] = x[(b * Nv + i0 + rr) * Dv + d];
    }
    for (int idx = tid; idx < 16384; idx += 1024) {
        int l = idx >> 8, d = idx & 255;
        Wt[d * 68 + l] = W[l * Dv + d];
    }
    __syncthreads();

    float a0 = 0.f, a1 = 0.f, a2 = 0.f, a3 = 0.f;
    int pr = tid & 15, pl0 = (tid >> 4) << 2;
    if (tid < 256) {
#pragma unroll 8
        for (int d = 0; d < 256; ++d) {
            float  xv = xs[d * 17 + pr];
            float4 wq = *(const float4*)&Wt[d * 68 + pl0];
            a0 = fmaf(xv, wq.x, a0);
            a1 = fmaf(xv, wq.y, a1);
            a2 = fmaf(xv, wq.z, a2);
            a3 = fmaf(xv, wq.w, a3);
        }
        a0 *= lw[pl0 + 0];
        a1 *= lw[pl0 + 1];
        a2 *= lw[pl0 + 2];
        a3 *= lw[pl0 + 3];
        float* dst = g_xh + b * (Lv * Nv) + i0 + pr;
        dst[(pl0 + 0) * Nv] = a0;
        dst[(pl0 + 1) * Nv] = a1;
        dst[(pl0 + 2) * Nv] = a2;
        dst[(pl0 + 3) * Nv] = a3;
    }
    __syncthreads();                 // xs dead; si2 region safe to write
    if (tid < 256) {
        si2[(pl0 + 0) * 16 + pr] = pk2(-a0);
        si2[(pl0 + 1) * 16 + pr] = pk2(-a1);
        si2[(pl0 + 2) * 16 + pr] = pk2(-a2);
        si2[(pl0 + 3) * 16 + pr] = pk2(-a3);
    }
    __syncthreads();

    // diagonal 16x16 block from si2 (lo halves hold -w*xhat)
    if (tid < 256) {
        int r = tid >> 4, c = tid & 15;
        const float* s = (const float*)si2;
        float acc = 0.f;
#pragma unroll 8
        for (int l = 0; l < 64; ++l)
            acc += fabsf(s[(l * 16 + r) * 2] - s[(l * 16 + c) * 2]);
        g_dist[(size_t)(b * Nv + i0 + r) * Nv + i0 + c] = acc;
    }

    grid_barrier(tid);

    // ---------------- stage j-band: window [i0, i0+272) mod 512 ------------
    for (int idx = tid; idx < 4352; idx += 1024) {
        int l = idx / 68, c4 = idx - l * 68;
        int jg4 = ((i0 >> 2) + c4) & 127;
        float4 v = *(const float4*)(g_xh + b * (Lv * Nv) + l * Nv + jg4 * 4);
        *(float4*)(sjb + l * 272 + c4 * 4) = v;
    }
    __syncthreads();

    // ---------------- mainloop: 16 rows x 256 band cols x 64 l -------------
    int w    = tid >> 5;
    int lane = tid & 31;
    int rg = w & 7;            // 2 rows: 2rg, 2rg+1
    int jq = (w >> 3) & 1;     // 128-col half of band
    int lh = w >> 4;           // l half

    const float* sjp = sjb + lh * 32 * 272 + 16 + jq * 128 + lane * 4;
    const ull*   sip = si2 + lh * 32 * 16 + rg * 2;
    const ull ABS2 = 0x7FFFFFFF7FFFFFFFull;
    ull a00 = 0, a01 = 0, a10 = 0, a11 = 0;

#pragma unroll
    for (int l = 0; l < 32; ++l) {
        ulonglong2 j01 = *(const ulonglong2*)(sjp + l * 272);
        ulonglong2 nab = *(const ulonglong2*)(sip + l * 16);
        a00 = add2(a00, add2(j01.x, nab.x) & ABS2);
        a01 = add2(a01, add2(j01.y, nab.x) & ABS2);
        a10 = add2(a10, add2(j01.x, nab.y) & ABS2);
        a11 = add2(a11, add2(j01.y, nab.y) & ABS2);
    }

    // merge l-halves in psum
    int prow = rg * 2, pcol = jq * 128 + lane * 4;
    if (lh == 0) {
        *(float4*)&psum[prow * 256 + pcol] =
            make_float4(lo2(a00), hi2(a00), lo2(a01), hi2(a01));
        *(float4*)&psum[(prow + 1) * 256 + pcol] =
            make_float4(lo2(a10), hi2(a10), lo2(a11), hi2(a11));
    }
    __syncthreads();
    if (lh == 1) {
        float4 p0 = *(const float4*)&psum[prow * 256 + pcol];
        p0.x += lo2(a00); p0.y += hi2(a00);
        p0.z += lo2(a01); p0.w += hi2(a01);
        *(float4*)&psum[prow * 256 + pcol] = p0;
        float4 p1 = *(const float4*)&psum[(prow + 1) * 256 + pcol];
        p1.x += lo2(a10); p1.y += hi2(a10);
        p1.z += lo2(a11); p1.w += hi2(a11);
        *(float4*)&psum[(prow + 1) * 256 + pcol] = p1;
    }
    __syncthreads();

    // direct write: rows i0.., band cols -> g_dist
    {
        int row = tid >> 6, c4 = tid & 63;
        float4 v = *(const float4*)&psum[row * 256 + c4 * 4];
        int jg = (i0 + 16 + c4 * 4) & 511;
        *(float4*)&g_dist[(size_t)(b * Nv + i0 + row) * Nv + jg] = v;
    }
    // transpose write: rows = band cols, cols = own rows
    {
        int jloc = tid >> 2, cg = tid & 3;
        float4 v;
        v.x = psum[(cg * 4 + 0) * 256 + jloc];
        v.y = psum[(cg * 4 + 1) * 256 + jloc];
        v.z = psum[(cg * 4 + 2) * 256 + jloc];
        v.w = psum[(cg * 4 + 3) * 256 + jloc];
        int jg = (i0 + 16 + jloc) & 511;
        *(float4*)&g_dist[(size_t)(b * Nv + jg) * Nv + i0 + cg * 4] = v;
    }

    grid_barrier(tid);

    // ---------------- Phase C: epilogue over own 16 full rows --------------
    {
        int row  = w >> 1;
        int half = w & 1;
        int c0 = half * 256 + lane * 4;
        int c1 = c0 + 128;
        const float* drow = g_dist + (size_t)(b * Nv + i0 + row) * Nv;
        const float* arow = adj    + (size_t)(b * Nv + i0 + row) * Nv;

        float4 v0 = __ldcg((const float4*)(drow + c0));
        float4 v1 = __ldcg((const float4*)(drow + c1));
        v0.x = v0.x > 0.f ? v0.x : 0.01f * v0.x;
        v0.y = v0.y > 0.f ? v0.y : 0.01f * v0.y;
        v0.z = v0.z > 0.f ? v0.z : 0.01f * v0.z;
        v0.w = v0.w > 0.f ? v0.w : 0.01f * v0.w;
        v1.x = v1.x > 0.f ? v1.x : 0.01f * v1.x;
        v1.y = v1.y > 0.f ? v1.y : 0.01f * v1.y;
        v1.z = v1.z > 0.f ? v1.z : 0.01f * v1.z;
        v1.w = v1.w > 0.f ? v1.w : 0.01f * v1.w;

        float4 A0 = __ldcg((const float4*)(arow + c0));
        float4 A1 = __ldcg((const float4*)(arow + c1));
        // no row-max needed: dist bounded (~36 +/- 5), exp stays finite
        float4 e0, e1;
        e0.x = A0.x * __expf(v0.x);
        e0.y = A0.y * __expf(v0.y);
        e0.z = A0.z * __expf(v0.z);
        e0.w = A0.w * __expf(v0.w);
        e1.x = A1.x * __expf(v1.x);
        e1.y = A1.y * __expf(v1.y);
        e1.z = A1.z * __expf(v1.z);
        e1.w = A1.w * __expf(v1.w);

        float sr = e0.x + e0.y + e0.z + e0.w + e1.x + e1.y + e1.z + e1.w;
#pragma unroll
        for (int o = 16; o; o >>= 1)
            sr += __shfl_xor_sync(0xffffffffu, sr, o);
        if (lane == 0) red[row * 2 + half] = sr;
        __syncthreads();
        float rs = 1.0f / (red[row * 2] + red[row * 2 + 1]);

        float* orow = out + (size_t)(b * Nv + i0 + row) * Nv;
        float4 o4;
        o4.x = e0.x * rs + 1e-10f; o4.y = e0.y * rs + 1e-10f;
        o4.z = e0.z * rs + 1e-10f; o4.w = e0.w * rs + 1e-10f;
        *(float4*)&orow[c0] = o4;
        o4.x = e1.x * rs + 1e-10f; o4.y = e1.y * rs + 1e-10f;
        o4.z = e1.z * rs + 1e-10f; o4.w = e1.w * rs + 1e-10f;
        *(float4*)&orow[c1] = o4;
    }
}

extern "C" void kernel_launch(void* const* d_in, const int* in_sizes, int n_in,
                              void* d_out, int out_size) {
    (void)in_sizes; (void)n_in; (void)out_size;
    const float* x   = (const float*)d_in[0];
    const float* adj = (const float*)d_in[1];
    const float* W   = (const float*)d_in[2];
    const float* lw  = (const float*)d_in[3];
    float* out = (float*)d_out;

    const int smem = 23616 * 4;   // 94464 B
    cudaFuncSetAttribute(fused_kernel,
                         cudaFuncAttributeMaxDynamicSharedMemorySize, smem);
    cudaFuncSetAttribute(fused_kernel,
                         cudaFuncAttributePreferredSharedMemoryCarveout,
                         cudaSharedmemCarveoutMaxShared);

    fused_kernel<<<Bv * 32, 1024, smem>>>(x, adj, W, lw, out);
}